// round 14
// baseline (speedup 1.0000x reference)
#include <cuda_runtime.h>
#include <cuda_fp16.h>
#include <cstdint>

typedef unsigned long long u64;
typedef unsigned int u32;
typedef unsigned short u16;

#define A_NODES 256
#define F_DIM   256
#define C_DIM   32

// ---------------- scratch (device globals; no runtime allocation) ------------
__device__ float g_right[A_NODES * C_DIM];                    // [b][d]
__device__ __half g_Ah[A_NODES * C_DIM];                      // [a][kpos(c)] fp16
__device__ __half g_Bh[(size_t)A_NODES * C_DIM * F_DIM];      // [b][c][f] fp16, 4 MB

// device-wide barrier state (epoch is monotonic -> graph-replay safe)
__device__ int g_cnt = 0;
__device__ volatile int g_epoch = 0;

// permuted position of k within a 16-col block: (2t,2t+1,2t+8,2t+9) adjacent
__device__ __host__ __forceinline__ int kpos(int k) {
    return (k & 1) | (((k >> 3) & 1) << 1) | (((k >> 1) & 3) << 2);
}

// ---------------- f32x2 helpers ----------------------------------------------
__device__ __forceinline__ u64 pack2(float x, float y) {
    u64 r; asm("mov.b64 %0, {%1, %2};" : "=l"(r) : "f"(x), "f"(y)); return r;
}
__device__ __forceinline__ void fma2(u64& d, u64 a, u64 b) {
    asm("fma.rn.f32x2 %0, %1, %2, %0;" : "+l"(d) : "l"(a), "l"(b));
}
__device__ __forceinline__ float2 unpack2(u64 v) {
    float2 f; asm("mov.b64 {%0, %1}, %2;" : "=f"(f.x), "=f"(f.y) : "l"(v)); return f;
}

// streaming (evict-first) 128-bit store
__device__ __forceinline__ void stg_cs_128(float* p, float4 v) {
    asm volatile("st.global.cs.v4.f32 [%0], {%1, %2, %3, %4};"
                 :: "l"(p), "f"(v.x), "f"(v.y), "f"(v.z), "f"(v.w) : "memory");
}

// ---------------- mma.sync fp16 ------------------------------------------------
__device__ __forceinline__ void mma_f16(float* d, const u32* a, const u32* b) {
    asm volatile("mma.sync.aligned.m16n8k16.row.col.f32.f16.f16.f32 "
        "{%0,%1,%2,%3}, {%4,%5,%6,%7}, {%8,%9}, {%0,%1,%2,%3};"
        : "+f"(d[0]), "+f"(d[1]), "+f"(d[2]), "+f"(d[3])
        : "r"(a[0]), "r"(a[1]), "r"(a[2]), "r"(a[3]), "r"(b[0]), "r"(b[1]));
}

// ---------------- Kernel A+B fused: lnproj -> grid barrier -> makeT ----------
// grid 256 x 256. occ 2 (regs ~110) => 296 resident slots >= 256 CTAs:
// all CTAs co-resident in wave 1, so the epoch spin cannot deadlock.
__global__ void __launch_bounds__(256, 2) k_prep(
        const float* __restrict__ nv, const float* __restrict__ mask,
        const float* __restrict__ lns, const float* __restrict__ lnb,
        const float* __restrict__ Wl, const float* __restrict__ bl,
        const float* __restrict__ Wr, const float* __restrict__ br,
        const float* __restrict__ Wo) {
    int blk = blockIdx.x, t = threadIdx.x;

    __shared__ float act[F_DIM];
    __shared__ float red[16];
    __shared__ float pls[256], prs[256];
    __shared__ float s_mu, s_rs;
    __shared__ __align__(16) float rT[32 * 32];
    __shared__ int s_e0;

    // ---- makeT identity for phase 2 ----
    int cT  = blk & 31;
    int b0T = (blk >> 5) * 32;

    // ---- Wo preload (independent of lnproj; hides LDG latency) ----
    u64 w2[32];
    #pragma unroll
    for (int d = 0; d < 32; d++) {
        float wv = Wo[(size_t)(cT * 32 + d) * F_DIM + t];
        w2[d] = pack2(wv, wv);
    }

    if (t == 0) s_e0 = g_epoch;   // snapshot before arriving (pre-bump safe)

    // ================= phase 1: lnproj for node a = blk =================
    {
        int a = blk;
        float x = nv[a * F_DIM + t];
        float s = x, s2 = x * x;
        #pragma unroll
        for (int o = 16; o; o >>= 1) {
            s  += __shfl_xor_sync(0xffffffffu, s,  o);
            s2 += __shfl_xor_sync(0xffffffffu, s2, o);
        }
        if ((t & 31) == 0) { red[t >> 5] = s; red[8 + (t >> 5)] = s2; }
        __syncthreads();
        if (t == 0) {
            float S = 0.f, S2 = 0.f;
            #pragma unroll
            for (int i = 0; i < 8; i++) { S += red[i]; S2 += red[8 + i]; }
            float m = S * (1.0f / F_DIM);
            float v = S2 * (1.0f / F_DIM) - m * m;
            s_mu = m;
            s_rs = rsqrtf(v + 1e-5f);
        }
        __syncthreads();
        act[t] = (x - s_mu) * s_rs * lns[t] + lnb[t];
        __syncthreads();

        int c = t & 31, ch = t >> 5;
        float pl = 0.f, pr = 0.f;
        #pragma unroll
        for (int k = 0; k < 32; k++) {
            int f = ch * 32 + k;
            float av = act[f];
            pl = fmaf(av, Wl[f * C_DIM + c], pl);
            pr = fmaf(av, Wr[f * C_DIM + c], pr);
        }
        pls[t] = pl; prs[t] = pr;
        __syncthreads();
        if (t < 32) {
            float L = bl[t], R = br[t];
            #pragma unroll
            for (int k = 0; k < 8; k++) { L += pls[k * 32 + t]; R += prs[k * 32 + t]; }
            float m = mask[a];
            g_right[a * C_DIM + t] = R * m;
            int pos = (t >> 4) * 16 + kpos(t & 15);
            g_Ah[a * 32 + pos] = __float2half_rn(L * m);
        }
    }
    __syncthreads();

    // ================= device-wide barrier (epoch) =================
    if (t == 0) {
        __threadfence();                       // publish g_right / g_Ah
        int e0 = s_e0;
        int my = atomicAdd(&g_cnt, 1);
        if (my == A_NODES - 1) {
            g_cnt = 0;                         // reset for next replay
            __threadfence();
            g_epoch = e0 + 1;                  // release
        }
        while (g_epoch == e0) { }              // spin (all CTAs resident)
    }
    __syncthreads();
    __threadfence();                           // acquire side

    // ================= phase 2: makeT for (cT, b0T) =================
    for (int i = t; i < 1024; i += 256) {
        int d = i >> 5, bl_ = i & 31;
        rT[d * 32 + bl_] = g_right[(b0T + bl_) * C_DIM + d];
    }
    __syncthreads();

    #pragma unroll
    for (int bq = 0; bq < 32; bq += 4) {
        u64 a0 = 0ULL, a1 = 0ULL;
        #pragma unroll
        for (int d = 0; d < 32; d++) {
            ulonglong2 r2 = *(const ulonglong2*)&rT[d * 32 + bq];
            fma2(a0, r2.x, w2[d]);
            fma2(a1, r2.y, w2[d]);
        }
        float2 v0 = unpack2(a0), v1 = unpack2(a1);
        __half* p = g_Bh + ((size_t)(b0T + bq) * C_DIM + cT) * F_DIM + t;
        p[0]                     = __float2half_rn(v0.x);
        p[1 * C_DIM * F_DIM]     = __float2half_rn(v0.y);
        p[2 * C_DIM * F_DIM]     = __float2half_rn(v1.x);
        p[3 * C_DIM * F_DIM]     = __float2half_rn(v1.y);
    }
}

// ---------------- Kernel C: fp16 single-pass mma.sync GEMM --------------------
// Grid (256 b, 2 mt, 4 nt) = 2048 CTAs. Tile M=128 x N=64, 8 warps, warp 32x32,
// K=32 (2 kblocks), 16 MMA per warp. acc=32 regs -> occ 3.
// B_s rows n-permuted so epilogue writes are STG.128 over 4 consecutive f.
#define LDA 48
#define LDB 52

__global__ void __launch_bounds__(256, 3) k_gemm(const float* __restrict__ bo,
                                                 float* __restrict__ out) {
    __shared__ __align__(16) u16 A_s[128 * LDA];
    __shared__ __align__(16) u16 B_s[64 * LDB];
    __shared__ __align__(16) float bo_s[64];

    int b  = blockIdx.x;
    int mt = blockIdx.y;
    int nt = blockIdx.z;
    int t = threadIdx.x, w = t >> 5, lane = t & 31;
    int g = lane >> 2, tig = lane & 3;
    int wm = w & 3, wn = w >> 2;
    int m0 = wm * 32, n0 = wn * 32;

    // --- A tile: 128 x 32 fp16 (kpos-permuted in g_Ah) ---
    #pragma unroll
    for (int i = 0; i < 2; i++) {
        int id = t + 256 * i;
        int m = id >> 2, q = id & 3;
        uint4 v = *(const uint4*)(g_Ah + ((size_t)mt * 128 + m) * 32 + q * 8);
        *(uint4*)(&A_s[m * LDA + q * 8]) = v;
    }

    // --- B tile: g_Bh[b][c][nt*64+f] -> B_s[r(f)][kpos(c)], u32 (f-pair) loads.
    {
        int c = t >> 3, fpb = t & 7;
        int pos = (c >> 4) * 16 + kpos(c & 15);
        const u32* src = (const u32*)(g_Bh + (size_t)b * (C_DIM * F_DIM) + c * F_DIM + nt * 64);
        #pragma unroll
        for (int j = 0; j < 4; j++) {
            int fp = fpb + 8 * j;
            u32 v = src[fp];
            int f = 2 * fp;
            int r = (f & ~15) + ((f & 2) << 2) + (((f >> 2) & 3) << 1);
            B_s[r * LDB + pos]       = (u16)(v & 0xffffu);
            B_s[(r + 1) * LDB + pos] = (u16)(v >> 16);
        }
    }
    if (t < 64) bo_s[t] = bo[nt * 64 + t];
    __syncthreads();

    float acc[2][4][4];
    #pragma unroll
    for (int mi = 0; mi < 2; mi++)
        #pragma unroll
        for (int ni = 0; ni < 4; ni++)
            #pragma unroll
            for (int q = 0; q < 4; q++) acc[mi][ni][q] = 0.f;

    #pragma unroll
    for (int kb = 0; kb < 2; kb++) {
        int col = kb * 16 + tig * 4;

        u32 af[2][4], bfr[4][2];
        #pragma unroll
        for (int mi = 0; mi < 2; mi++) {
            int row = m0 + mi * 16 + g;
            uint2 v0 = *(const uint2*)&A_s[row * LDA + col];
            uint2 v1 = *(const uint2*)&A_s[(row + 8) * LDA + col];
            af[mi][0] = v0.x; af[mi][2] = v0.y;
            af[mi][1] = v1.x; af[mi][3] = v1.y;
        }
        #pragma unroll
        for (int ni = 0; ni < 4; ni++) {
            uint2 v = *(const uint2*)&B_s[(n0 + ni * 8 + g) * LDB + col];
            bfr[ni][0] = v.x; bfr[ni][1] = v.y;
        }
        #pragma unroll
        for (int mi = 0; mi < 2; mi++)
            #pragma unroll
            for (int ni = 0; ni < 4; ni++)
                mma_f16(acc[mi][ni], af[mi], bfr[ni]);
    }

    // --- epilogue: STG.128 (.cs), thread (g,tig) owns f = (wn*2+p)*16 + 4*tig ---
    #pragma unroll
    for (int mi = 0; mi < 2; mi++) {
        size_t a_row = (size_t)mt * 128 + m0 + mi * 16 + g;
        float* prow  = out + a_row * ((size_t)A_NODES * F_DIM) + (size_t)b * F_DIM + nt * 64;
        float* prow8 = prow + 8 * ((size_t)A_NODES * F_DIM);
        #pragma unroll
        for (int p = 0; p < 2; p++) {
            int ni0 = 2 * p, ni1 = 2 * p + 1;
            int fl = (wn * 2 + p) * 16 + tig * 4;
            float4 bv = *(const float4*)&bo_s[fl];
            float4 w0, w1;
            w0.x = acc[mi][ni0][0] + bv.x; w0.y = acc[mi][ni0][1] + bv.y;
            w0.z = acc[mi][ni1][0] + bv.z; w0.w = acc[mi][ni1][1] + bv.w;
            w1.x = acc[mi][ni0][2] + bv.x; w1.y = acc[mi][ni0][3] + bv.y;
            w1.z = acc[mi][ni1][2] + bv.z; w1.w = acc[mi][ni1][3] + bv.w;
            stg_cs_128(prow + fl,  w0);
            stg_cs_128(prow8 + fl, w1);
        }
    }
}

// ---------------- launch ------------------------------------------------------
extern "C" void kernel_launch(void* const* d_in, const int* in_sizes, int n_in,
                              void* d_out, int out_size) {
    const float* nv   = (const float*)d_in[0];
    const float* mask = (const float*)d_in[1];
    const float* lns  = (const float*)d_in[2];
    const float* lnb  = (const float*)d_in[3];
    const float* Wl   = (const float*)d_in[4];
    const float* bl   = (const float*)d_in[5];
    const float* Wr   = (const float*)d_in[6];
    const float* br   = (const float*)d_in[7];
    const float* Wo   = (const float*)d_in[8];
    const float* bo   = (const float*)d_in[9];
    float* out = (float*)d_out;

    k_prep<<<A_NODES, 256>>>(nv, mask, lns, lnb, Wl, bl, Wr, br, Wo);
    k_gemm<<<dim3(256, 2, 4), 256>>>(bo, out);
}

// round 15
// speedup vs baseline: 1.5173x; 1.5173x over previous
#include <cuda_runtime.h>
#include <cuda_fp16.h>
#include <cstdint>

typedef unsigned long long u64;
typedef unsigned int u32;
typedef unsigned short u16;

#define A_NODES 256
#define F_DIM   256
#define C_DIM   32

// ---------------- scratch (device globals; no runtime allocation) ------------
__device__ float g_right[A_NODES * C_DIM];                    // [b][d]
__device__ __align__(16) __half g_Ah[A_NODES * C_DIM];        // [a][s(c)] fp16, tig-major
__device__ __half g_Bh[(size_t)A_NODES * C_DIM * F_DIM];      // [b][c][f] fp16, 4 MB

// kpos: permuted position of k within a 16-col block (B operand, unchanged)
__device__ __host__ __forceinline__ int kpos(int k) {
    return (k & 1) | (((k >> 3) & 1) << 1) | (((k >> 1) & 3) << 2);
}
// s(c): A operand storage — tig-major so one LDG.128 per row covers both kblocks
// s = tig(c)*8 + kb*4 + hi8*2 + odd
__device__ __forceinline__ int apos(int c) {
    return ((c >> 1) & 3) * 8 + ((c >> 4) & 1) * 4 + ((c >> 3) & 1) * 2 + (c & 1);
}

// ---------------- f32x2 helpers ----------------------------------------------
__device__ __forceinline__ u64 pack2(float x, float y) {
    u64 r; asm("mov.b64 %0, {%1, %2};" : "=l"(r) : "f"(x), "f"(y)); return r;
}
__device__ __forceinline__ void fma2(u64& d, u64 a, u64 b) {
    asm("fma.rn.f32x2 %0, %1, %2, %0;" : "+l"(d) : "l"(a), "l"(b));
}
__device__ __forceinline__ float2 unpack2(u64 v) {
    float2 f; asm("mov.b64 {%0, %1}, %2;" : "=f"(f.x), "=f"(f.y) : "l"(v)); return f;
}

// streaming (evict-first) 128-bit store
__device__ __forceinline__ void stg_cs_128(float* p, float4 v) {
    asm volatile("st.global.cs.v4.f32 [%0], {%1, %2, %3, %4};"
                 :: "l"(p), "f"(v.x), "f"(v.y), "f"(v.z), "f"(v.w) : "memory");
}

// ---------------- mma.sync fp16 ------------------------------------------------
__device__ __forceinline__ void mma_f16(float* d, const u32* a, const u32* b) {
    asm volatile("mma.sync.aligned.m16n8k16.row.col.f32.f16.f16.f32 "
        "{%0,%1,%2,%3}, {%4,%5,%6,%7}, {%8,%9}, {%0,%1,%2,%3};"
        : "+f"(d[0]), "+f"(d[1]), "+f"(d[2]), "+f"(d[3])
        : "r"(a[0]), "r"(a[1]), "r"(a[2]), "r"(a[3]), "r"(b[0]), "r"(b[1]));
}

// ---------------- Kernel A: LayerNorm + dual projections ----------------------
// (block per node, 256 threads — proven config)
__global__ void k_lnproj(const float* __restrict__ nv, const float* __restrict__ mask,
                         const float* __restrict__ lns, const float* __restrict__ lnb,
                         const float* __restrict__ Wl, const float* __restrict__ bl,
                         const float* __restrict__ Wr, const float* __restrict__ br) {
    int a = blockIdx.x, t = threadIdx.x;
    __shared__ float act[F_DIM];
    __shared__ float red[16];
    __shared__ float pls[256], prs[256];
    __shared__ float s_mu, s_rs;

    float x = nv[a * F_DIM + t];
    float s = x, s2 = x * x;
    #pragma unroll
    for (int o = 16; o; o >>= 1) {
        s  += __shfl_xor_sync(0xffffffffu, s,  o);
        s2 += __shfl_xor_sync(0xffffffffu, s2, o);
    }
    if ((t & 31) == 0) { red[t >> 5] = s; red[8 + (t >> 5)] = s2; }
    __syncthreads();
    if (t == 0) {
        float S = 0.f, S2 = 0.f;
        #pragma unroll
        for (int i = 0; i < 8; i++) { S += red[i]; S2 += red[8 + i]; }
        float m = S * (1.0f / F_DIM);
        float v = S2 * (1.0f / F_DIM) - m * m;
        s_mu = m;
        s_rs = rsqrtf(v + 1e-5f);
    }
    __syncthreads();
    act[t] = (x - s_mu) * s_rs * lns[t] + lnb[t];
    __syncthreads();

    int c = t & 31, ch = t >> 5;
    float pl = 0.f, pr = 0.f;
    #pragma unroll
    for (int k = 0; k < 32; k++) {
        int f = ch * 32 + k;
        float av = act[f];
        pl = fmaf(av, Wl[f * C_DIM + c], pl);
        pr = fmaf(av, Wr[f * C_DIM + c], pr);
    }
    pls[t] = pl; prs[t] = pr;
    __syncthreads();
    if (t < 32) {
        float L = bl[t], R = br[t];
        #pragma unroll
        for (int k = 0; k < 8; k++) { L += pls[k * 32 + t]; R += prs[k * 32 + t]; }
        float m = mask[a];
        g_right[a * C_DIM + t] = R * m;
        g_Ah[a * 32 + apos(t)] = __float2half_rn(L * m);
    }
}

// ---------------- Kernel B: T[b,c,f] = sum_d right[b,d]*Wo[c*32+d,f] -> fp16 --
__global__ void __launch_bounds__(256, 2) k_makeT(const float* __restrict__ Wo) {
    int c  = blockIdx.x;
    int b0 = blockIdx.y * 32;
    int f  = threadIdx.x;

    __shared__ __align__(16) float rT[32 * 32];

    u64 w2[32];
    #pragma unroll
    for (int d = 0; d < 32; d++) {
        float wv = Wo[(size_t)(c * 32 + d) * F_DIM + f];
        w2[d] = pack2(wv, wv);
    }
    for (int i = f; i < 1024; i += 256) {
        int d = i >> 5, bl_ = i & 31;
        rT[d * 32 + bl_] = g_right[(b0 + bl_) * C_DIM + d];
    }
    __syncthreads();

    #pragma unroll
    for (int bq = 0; bq < 32; bq += 4) {
        u64 a0 = 0ULL, a1 = 0ULL;
        #pragma unroll
        for (int d = 0; d < 32; d++) {
            ulonglong2 r2 = *(const ulonglong2*)&rT[d * 32 + bq];
            fma2(a0, r2.x, w2[d]);
            fma2(a1, r2.y, w2[d]);
        }
        float2 v0 = unpack2(a0), v1 = unpack2(a1);
        __half* p = g_Bh + ((size_t)(b0 + bq) * C_DIM + c) * F_DIM + f;
        p[0]                     = __float2half_rn(v0.x);
        p[1 * C_DIM * F_DIM]     = __float2half_rn(v0.y);
        p[2 * C_DIM * F_DIM]     = __float2half_rn(v1.x);
        p[3 * C_DIM * F_DIM]     = __float2half_rn(v1.y);
    }
}

// ---------------- Kernel C: fp16 single-pass mma.sync GEMM --------------------
// Grid (256 b, 2 mt, 4 nt) = 2048 CTAs. Tile M=128 x N=64, 8 warps, warp 32x32,
// K=32 (2 kblocks), 16 MMA per warp. occ 3.
// A fragments loaded DIRECTLY from gmem (g_Ah is 16KB -> L1/L2 resident):
// no A smem fill, no A LDS in mainloop. B via smem (kpos + r(f) permutations).
#define LDB 52

__global__ void __launch_bounds__(256, 3) k_gemm(const float* __restrict__ bo,
                                                 float* __restrict__ out) {
    __shared__ __align__(16) u16 B_s[64 * LDB];
    __shared__ __align__(16) float bo_s[64];

    int b  = blockIdx.x;
    int mt = blockIdx.y;
    int nt = blockIdx.z;
    int t = threadIdx.x, w = t >> 5, lane = t & 31;
    int g = lane >> 2, tig = lane & 3;
    int wm = w & 3, wn = w >> 2;
    int m0 = wm * 32, n0 = wn * 32;

    // --- A fragments: 4x LDG.128, fully coalesced (512B contiguous per warp) ---
    u32 af[2][2][4];   // [kb][mi][reg]
    {
        const uint4* A4 = (const uint4*)g_Ah;   // u16 idx row*32 + tig*8 -> uint4 idx row*4 + tig
        #pragma unroll
        for (int mi = 0; mi < 2; mi++) {
            int row = mt * 128 + m0 + mi * 16 + g;
            uint4 v0 = A4[row * 4 + tig];
            uint4 v1 = A4[(row + 8) * 4 + tig];
            af[0][mi][0] = v0.x; af[0][mi][2] = v0.y;
            af[1][mi][0] = v0.z; af[1][mi][2] = v0.w;
            af[0][mi][1] = v1.x; af[0][mi][3] = v1.y;
            af[1][mi][1] = v1.z; af[1][mi][3] = v1.w;
        }
    }

    // --- B tile: g_Bh[b][c][nt*64+f] -> B_s[r(f)][kpos(c)], u32 (f-pair) loads.
    {
        int c = t >> 3, fpb = t & 7;
        int pos = (c >> 4) * 16 + kpos(c & 15);
        const u32* src = (const u32*)(g_Bh + (size_t)b * (C_DIM * F_DIM) + c * F_DIM + nt * 64);
        #pragma unroll
        for (int j = 0; j < 4; j++) {
            int fp = fpb + 8 * j;
            u32 v = src[fp];
            int f = 2 * fp;
            int r = (f & ~15) + ((f & 2) << 2) + (((f >> 2) & 3) << 1);
            B_s[r * LDB + pos]       = (u16)(v & 0xffffu);
            B_s[(r + 1) * LDB + pos] = (u16)(v >> 16);
        }
    }
    if (t < 64) bo_s[t] = bo[nt * 64 + t];
    __syncthreads();

    float acc[2][4][4];
    #pragma unroll
    for (int mi = 0; mi < 2; mi++)
        #pragma unroll
        for (int ni = 0; ni < 4; ni++)
            #pragma unroll
            for (int q = 0; q < 4; q++) acc[mi][ni][q] = 0.f;

    #pragma unroll
    for (int kb = 0; kb < 2; kb++) {
        int col = kb * 16 + tig * 4;

        u32 bfr[4][2];
        #pragma unroll
        for (int ni = 0; ni < 4; ni++) {
            uint2 v = *(const uint2*)&B_s[(n0 + ni * 8 + g) * LDB + col];
            bfr[ni][0] = v.x; bfr[ni][1] = v.y;
        }
        #pragma unroll
        for (int mi = 0; mi < 2; mi++)
            #pragma unroll
            for (int ni = 0; ni < 4; ni++)
                mma_f16(acc[mi][ni], af[kb][mi], bfr[ni]);
    }

    // --- epilogue: STG.128 (.cs), thread (g,tig) owns f = (wn*2+p)*16 + 4*tig ---
    #pragma unroll
    for (int mi = 0; mi < 2; mi++) {
        size_t a_row = (size_t)mt * 128 + m0 + mi * 16 + g;
        float* prow  = out + a_row * ((size_t)A_NODES * F_DIM) + (size_t)b * F_DIM + nt * 64;
        float* prow8 = prow + 8 * ((size_t)A_NODES * F_DIM);
        #pragma unroll
        for (int p = 0; p < 2; p++) {
            int ni0 = 2 * p, ni1 = 2 * p + 1;
            int fl = (wn * 2 + p) * 16 + tig * 4;
            float4 bv = *(const float4*)&bo_s[fl];
            float4 w0, w1;
            w0.x = acc[mi][ni0][0] + bv.x; w0.y = acc[mi][ni0][1] + bv.y;
            w0.z = acc[mi][ni1][0] + bv.z; w0.w = acc[mi][ni1][1] + bv.w;
            w1.x = acc[mi][ni0][2] + bv.x; w1.y = acc[mi][ni0][3] + bv.y;
            w1.z = acc[mi][ni1][2] + bv.z; w1.w = acc[mi][ni1][3] + bv.w;
            stg_cs_128(prow + fl,  w0);
            stg_cs_128(prow8 + fl, w1);
        }
    }
}

// ---------------- launch ------------------------------------------------------
extern "C" void kernel_launch(void* const* d_in, const int* in_sizes, int n_in,
                              void* d_out, int out_size) {
    const float* nv   = (const float*)d_in[0];
    const float* mask = (const float*)d_in[1];
    const float* lns  = (const float*)d_in[2];
    const float* lnb  = (const float*)d_in[3];
    const float* Wl   = (const float*)d_in[4];
    const float* bl   = (const float*)d_in[5];
    const float* Wr   = (const float*)d_in[6];
    const float* br   = (const float*)d_in[7];
    const float* Wo   = (const float*)d_in[8];
    const float* bo   = (const float*)d_in[9];
    float* out = (float*)d_out;

    k_lnproj<<<A_NODES, 256>>>(nv, mask, lns, lnb, Wl, bl, Wr, br);
    k_makeT<<<dim3(32, 8), 256>>>(Wo);
    k_gemm<<<dim3(256, 2, 4), 256>>>(bo, out);
}

// round 16
// speedup vs baseline: 1.6164x; 1.0653x over previous
#include <cuda_runtime.h>
#include <cuda_fp16.h>
#include <cstdint>

typedef unsigned long long u64;
typedef unsigned int u32;
typedef unsigned short u16;

#define A_NODES 256
#define F_DIM   256
#define C_DIM   32

// ---------------- scratch (device globals; no runtime allocation) ------------
__device__ float g_right[A_NODES * C_DIM];                    // [b][d]
__device__ __align__(16) __half g_Ah[A_NODES * C_DIM];        // [a][apos(c)] fp16
__device__ __align__(16) __half g_Bh[(size_t)A_NODES * C_DIM * F_DIM];  // [b][c][Rj(f)] fp16, 4 MB

// apos: A storage — tig-major so one LDG.128 per row yields canonical a-frags
__device__ __forceinline__ int apos(int c) {
    return ((c >> 1) & 3) * 8 + ((c >> 4) & 1) * 4 + ((c >> 3) & 1) * 2 + (c & 1);
}
// Rj: f-column permutation (within 16-f groups) so mma n-index maps to 4
// consecutive global f per thread -> STG.128 epilogue.
__device__ __forceinline__ int rjpos(int f) {
    return (f & ~15) | ((f & 2) << 2) | (((f >> 2) & 3) << 1) | (f & 1);
}

// ---------------- helpers ------------------------------------------------------
__device__ __forceinline__ u32 smem_u32(const void* p) {
    u32 a; asm("{ .reg .u64 t; cvta.to.shared.u64 t, %1; cvt.u32.u64 %0, t; }" : "=r"(a) : "l"(p));
    return a;
}
__device__ __forceinline__ u64 pack2(float x, float y) {
    u64 r; asm("mov.b64 %0, {%1, %2};" : "=l"(r) : "f"(x), "f"(y)); return r;
}
__device__ __forceinline__ void fma2(u64& d, u64 a, u64 b) {
    asm("fma.rn.f32x2 %0, %1, %2, %0;" : "+l"(d) : "l"(a), "l"(b));
}
__device__ __forceinline__ float2 unpack2(u64 v) {
    float2 f; asm("mov.b64 {%0, %1}, %2;" : "=f"(f.x), "=f"(f.y) : "l"(v)); return f;
}
__device__ __forceinline__ void stg_cs_128(float* p, float4 v) {
    asm volatile("st.global.cs.v4.f32 [%0], {%1, %2, %3, %4};"
                 :: "l"(p), "f"(v.x), "f"(v.y), "f"(v.z), "f"(v.w) : "memory");
}
__device__ __forceinline__ void ldsm_x2_t(u32& r0, u32& r1, u32 saddr) {
    asm volatile("ldmatrix.sync.aligned.m8n8.x2.trans.shared.b16 {%0, %1}, [%2];"
                 : "=r"(r0), "=r"(r1) : "r"(saddr));
}
__device__ __forceinline__ void mma_f16(float* d, const u32* a, const u32* b) {
    asm volatile("mma.sync.aligned.m16n8k16.row.col.f32.f16.f16.f32 "
        "{%0,%1,%2,%3}, {%4,%5,%6,%7}, {%8,%9}, {%0,%1,%2,%3};"
        : "+f"(d[0]), "+f"(d[1]), "+f"(d[2]), "+f"(d[3])
        : "r"(a[0]), "r"(a[1]), "r"(a[2]), "r"(a[3]), "r"(b[0]), "r"(b[1]));
}

// ---------------- Kernel A: LayerNorm + dual projections ----------------------
__global__ void k_lnproj(const float* __restrict__ nv, const float* __restrict__ mask,
                         const float* __restrict__ lns, const float* __restrict__ lnb,
                         const float* __restrict__ Wl, const float* __restrict__ bl,
                         const float* __restrict__ Wr, const float* __restrict__ br) {
    int a = blockIdx.x, t = threadIdx.x;
    __shared__ float act[F_DIM];
    __shared__ float red[16];
    __shared__ float pls[256], prs[256];
    __shared__ float s_mu, s_rs;

    float x = nv[a * F_DIM + t];
    float s = x, s2 = x * x;
    #pragma unroll
    for (int o = 16; o; o >>= 1) {
        s  += __shfl_xor_sync(0xffffffffu, s,  o);
        s2 += __shfl_xor_sync(0xffffffffu, s2, o);
    }
    if ((t & 31) == 0) { red[t >> 5] = s; red[8 + (t >> 5)] = s2; }
    __syncthreads();
    if (t == 0) {
        float S = 0.f, S2 = 0.f;
        #pragma unroll
        for (int i = 0; i < 8; i++) { S += red[i]; S2 += red[8 + i]; }
        float m = S * (1.0f / F_DIM);
        float v = S2 * (1.0f / F_DIM) - m * m;
        s_mu = m;
        s_rs = rsqrtf(v + 1e-5f);
    }
    __syncthreads();
    act[t] = (x - s_mu) * s_rs * lns[t] + lnb[t];
    __syncthreads();

    int c = t & 31, ch = t >> 5;
    float pl = 0.f, pr = 0.f;
    #pragma unroll
    for (int k = 0; k < 32; k++) {
        int f = ch * 32 + k;
        float av = act[f];
        pl = fmaf(av, Wl[f * C_DIM + c], pl);
        pr = fmaf(av, Wr[f * C_DIM + c], pr);
    }
    pls[t] = pl; prs[t] = pr;
    __syncthreads();
    if (t < 32) {
        float L = bl[t], R = br[t];
        #pragma unroll
        for (int k = 0; k < 8; k++) { L += pls[k * 32 + t]; R += prs[k * 32 + t]; }
        float m = mask[a];
        g_right[a * C_DIM + t] = R * m;
        g_Ah[a * 32 + apos(t)] = __float2half_rn(L * m);
    }
}

// ---------------- Kernel B: T[b,c,f] = sum_d right[b,d]*Wo[c*32+d,f] -> fp16 --
// Writes f at permuted column Rj(f) (within-sector permutation, coalescing kept).
__global__ void __launch_bounds__(256, 2) k_makeT(const float* __restrict__ Wo) {
    int c  = blockIdx.x;
    int b0 = blockIdx.y * 32;
    int f  = threadIdx.x;

    __shared__ __align__(16) float rT[32 * 32];

    u64 w2[32];
    #pragma unroll
    for (int d = 0; d < 32; d++) {
        float wv = Wo[(size_t)(c * 32 + d) * F_DIM + f];
        w2[d] = pack2(wv, wv);
    }
    for (int i = f; i < 1024; i += 256) {
        int d = i >> 5, bl_ = i & 31;
        rT[d * 32 + bl_] = g_right[(b0 + bl_) * C_DIM + d];
    }
    __syncthreads();

    int jf = rjpos(f);
    #pragma unroll
    for (int bq = 0; bq < 32; bq += 4) {
        u64 a0 = 0ULL, a1 = 0ULL;
        #pragma unroll
        for (int d = 0; d < 32; d++) {
            ulonglong2 r2 = *(const ulonglong2*)&rT[d * 32 + bq];
            fma2(a0, r2.x, w2[d]);
            fma2(a1, r2.y, w2[d]);
        }
        float2 v0 = unpack2(a0), v1 = unpack2(a1);
        __half* p = g_Bh + ((size_t)(b0 + bq) * C_DIM + c) * F_DIM + jf;
        p[0]                     = __float2half_rn(v0.x);
        p[1 * C_DIM * F_DIM]     = __float2half_rn(v0.y);
        p[2 * C_DIM * F_DIM]     = __float2half_rn(v1.x);
        p[3 * C_DIM * F_DIM]     = __float2half_rn(v1.y);
    }
}

// ---------------- Kernel C: fp16 mma.sync GEMM with ldmatrix B ----------------
// Grid (256 b, 2 mt, 4 nt) = 2048 CTAs. Tile M=128 x N=64, 8 warps, warp 32x32.
// A frags: direct LDG.128 from g_Ah (canonical a-frag layout).
// B: straight-copy smem tile [c=32][f-window 64], rows padded to 144B;
//    fragments via ldmatrix.x2.trans (natural k-order). No pack/unpack scatter.
#define LDBp 72   // u16 per row (144 B: 16B-aligned, LDSM conflict-free)

__global__ void __launch_bounds__(256, 3) k_gemm(const float* __restrict__ bo,
                                                 float* __restrict__ out) {
    __shared__ __align__(16) u16 B_s[32 * LDBp];

    int b  = blockIdx.x;
    int mt = blockIdx.y;
    int nt = blockIdx.z;
    int t = threadIdx.x, w = t >> 5, lane = t & 31;
    int g = lane >> 2, tig = lane & 3;
    int wm = w & 3, wn = w >> 2;
    int m0 = wm * 32, n0 = wn * 32;

    // --- A fragments: 4x LDG.128, fully coalesced ---
    u32 af[2][2][4];   // [kb][mi][reg]
    {
        const uint4* A4 = (const uint4*)g_Ah;
        #pragma unroll
        for (int mi = 0; mi < 2; mi++) {
            int row = mt * 128 + m0 + mi * 16 + g;
            uint4 v0 = A4[row * 4 + tig];
            uint4 v1 = A4[(row + 8) * 4 + tig];
            af[0][mi][0] = v0.x; af[0][mi][2] = v0.y;
            af[1][mi][0] = v0.z; af[1][mi][2] = v0.w;
            af[0][mi][1] = v1.x; af[0][mi][3] = v1.y;
            af[1][mi][1] = v1.z; af[1][mi][3] = v1.w;
        }
    }

    // --- B tile: straight copy, 1 LDG.128 + 1 STS.128 per thread ---
    {
        int cc = t >> 3, q = t & 7;
        uint4 v = *(const uint4*)(g_Bh + ((size_t)b * C_DIM + cc) * F_DIM + nt * 64 + q * 8);
        *(uint4*)&B_s[cc * LDBp + q * 8] = v;
    }

    // --- bo: direct, 2x float4 (f = nt*64 + (wn*2+p)*16 + tig*4) ---
    float4 bv0 = __ldg((const float4*)&bo[nt * 64 + (wn * 2) * 16 + tig * 4]);
    float4 bv1 = __ldg((const float4*)&bo[nt * 64 + (wn * 2 + 1) * 16 + tig * 4]);
    __syncthreads();

    float acc[2][4][4];
    #pragma unroll
    for (int mi = 0; mi < 2; mi++)
        #pragma unroll
        for (int ni = 0; ni < 4; ni++)
            #pragma unroll
            for (int q = 0; q < 4; q++) acc[mi][ni][q] = 0.f;

    u32 sbase = smem_u32(B_s);
    #pragma unroll
    for (int kb = 0; kb < 2; kb++) {
        u32 rowaddr = sbase + ((kb * 16 + (lane & 15)) * LDBp) * 2;
        u32 bfr[4][2];
        #pragma unroll
        for (int ni = 0; ni < 4; ni++)
            ldsm_x2_t(bfr[ni][0], bfr[ni][1], rowaddr + (n0 + ni * 8) * 2);
        #pragma unroll
        for (int mi = 0; mi < 2; mi++)
            #pragma unroll
            for (int ni = 0; ni < 4; ni++)
                mma_f16(acc[mi][ni], af[kb][mi], bfr[ni]);
    }

    // --- epilogue: STG.128 (.cs), thread (g,tig) owns f = (wn*2+p)*16 + 4*tig ---
    #pragma unroll
    for (int mi = 0; mi < 2; mi++) {
        size_t a_row = (size_t)mt * 128 + m0 + mi * 16 + g;
        float* prow  = out + a_row * ((size_t)A_NODES * F_DIM) + (size_t)b * F_DIM + nt * 64;
        float* prow8 = prow + 8 * ((size_t)A_NODES * F_DIM);
        #pragma unroll
        for (int p = 0; p < 2; p++) {
            int ni0 = 2 * p, ni1 = 2 * p + 1;
            int fl = (wn * 2 + p) * 16 + tig * 4;
            float4 bv = p ? bv1 : bv0;
            float4 w0, w1;
            w0.x = acc[mi][ni0][0] + bv.x; w0.y = acc[mi][ni0][1] + bv.y;
            w0.z = acc[mi][ni1][0] + bv.z; w0.w = acc[mi][ni1][1] + bv.w;
            w1.x = acc[mi][ni0][2] + bv.x; w1.y = acc[mi][ni0][3] + bv.y;
            w1.z = acc[mi][ni1][2] + bv.z; w1.w = acc[mi][ni1][3] + bv.w;
            stg_cs_128(prow + fl,  w0);
            stg_cs_128(prow8 + fl, w1);
        }
    }
}

// ---------------- launch ------------------------------------------------------
extern "C" void kernel_launch(void* const* d_in, const int* in_sizes, int n_in,
                              void* d_out, int out_size) {
    const float* nv   = (const float*)d_in[0];
    const float* mask = (const float*)d_in[1];
    const float* lns  = (const float*)d_in[2];
    const float* lnb  = (const float*)d_in[3];
    const float* Wl   = (const float*)d_in[4];
    const float* bl   = (const float*)d_in[5];
    const float* Wr   = (const float*)d_in[6];
    const float* br   = (const float*)d_in[7];
    const float* Wo   = (const float*)d_in[8];
    const float* bo   = (const float*)d_in[9];
    float* out = (float*)d_out;

    k_lnproj<<<A_NODES, 256>>>(nv, mask, lns, lnb, Wl, bl, Wr, br);
    k_makeT<<<dim3(32, 8), 256>>>(Wo);
    k_gemm<<<dim3(256, 2, 4), 256>>>(bo, out);
}

// round 17
// speedup vs baseline: 1.8721x; 1.1582x over previous
#include <cuda_runtime.h>
#include <cuda_fp16.h>
#include <cstdint>

typedef unsigned long long u64;
typedef unsigned int u32;
typedef unsigned short u16;

#define A_NODES 256
#define F_DIM   256
#define C_DIM   32

// ---------------- scratch (device globals; no runtime allocation) ------------
__device__ __align__(16) __half g_Ah[A_NODES * C_DIM];        // left:  [a][apos(c)] fp16
__device__ __align__(16) __half g_RhH[A_NODES * C_DIM];       // right: [b][apos(d)] fp16
__device__ __align__(16) __half g_Bh[(size_t)A_NODES * C_DIM * F_DIM];  // [b][c*256+Rj(f)] fp16, 4 MB

// apos: A-operand storage — tig-major so one LDG.128 per row yields canonical a-frags
__device__ __forceinline__ int apos(int c) {
    return ((c >> 1) & 3) * 8 + ((c >> 4) & 1) * 4 + ((c >> 3) & 1) * 2 + (c & 1);
}

// ---------------- helpers ------------------------------------------------------
__device__ __forceinline__ u32 smem_u32(const void* p) {
    u32 a; asm("{ .reg .u64 t; cvta.to.shared.u64 t, %1; cvt.u32.u64 %0, t; }" : "=r"(a) : "l"(p));
    return a;
}
__device__ __forceinline__ void stg_cs_128(float* p, float4 v) {
    asm volatile("st.global.cs.v4.f32 [%0], {%1, %2, %3, %4};"
                 :: "l"(p), "f"(v.x), "f"(v.y), "f"(v.z), "f"(v.w) : "memory");
}
__device__ __forceinline__ void ldsm_x2_t(u32& r0, u32& r1, u32 saddr) {
    asm volatile("ldmatrix.sync.aligned.m8n8.x2.trans.shared.b16 {%0, %1}, [%2];"
                 : "=r"(r0), "=r"(r1) : "r"(saddr));
}
__device__ __forceinline__ void mma_f16(float* d, const u32* a, const u32* b) {
    asm volatile("mma.sync.aligned.m16n8k16.row.col.f32.f16.f16.f32 "
        "{%0,%1,%2,%3}, {%4,%5,%6,%7}, {%8,%9}, {%0,%1,%2,%3};"
        : "+f"(d[0]), "+f"(d[1]), "+f"(d[2]), "+f"(d[3])
        : "r"(a[0]), "r"(a[1]), "r"(a[2]), "r"(a[3]), "r"(b[0]), "r"(b[1]));
}

// ---------------- Kernel A: LayerNorm + dual projections ----------------------
__global__ void k_lnproj(const float* __restrict__ nv, const float* __restrict__ mask,
                         const float* __restrict__ lns, const float* __restrict__ lnb,
                         const float* __restrict__ Wl, const float* __restrict__ bl,
                         const float* __restrict__ Wr, const float* __restrict__ br) {
    int a = blockIdx.x, t = threadIdx.x;
    __shared__ float act[F_DIM];
    __shared__ float red[16];
    __shared__ float pls[256], prs[256];
    __shared__ float s_mu, s_rs;

    float x = nv[a * F_DIM + t];
    float s = x, s2 = x * x;
    #pragma unroll
    for (int o = 16; o; o >>= 1) {
        s  += __shfl_xor_sync(0xffffffffu, s,  o);
        s2 += __shfl_xor_sync(0xffffffffu, s2, o);
    }
    if ((t & 31) == 0) { red[t >> 5] = s; red[8 + (t >> 5)] = s2; }
    __syncthreads();
    if (t == 0) {
        float S = 0.f, S2 = 0.f;
        #pragma unroll
        for (int i = 0; i < 8; i++) { S += red[i]; S2 += red[8 + i]; }
        float m = S * (1.0f / F_DIM);
        float v = S2 * (1.0f / F_DIM) - m * m;
        s_mu = m;
        s_rs = rsqrtf(v + 1e-5f);
    }
    __syncthreads();
    act[t] = (x - s_mu) * s_rs * lns[t] + lnb[t];
    __syncthreads();

    int c = t & 31, ch = t >> 5;
    float pl = 0.f, pr = 0.f;
    #pragma unroll
    for (int k = 0; k < 32; k++) {
        int f = ch * 32 + k;
        float av = act[f];
        pl = fmaf(av, Wl[f * C_DIM + c], pl);
        pr = fmaf(av, Wr[f * C_DIM + c], pr);
    }
    pls[t] = pl; prs[t] = pr;
    __syncthreads();
    if (t < 32) {
        float L = bl[t], R = br[t];
        #pragma unroll
        for (int k = 0; k < 8; k++) { L += pls[k * 32 + t]; R += prs[k * 32 + t]; }
        float m = mask[a];
        int ap = apos(t);
        g_Ah[a * 32 + ap]  = __float2half_rn(L * m);
        g_RhH[a * 32 + ap] = __float2half_rn(R * m);
    }
}

// ---------------- Kernel B: tensor-core makeT ---------------------------------
// T = right[256x32] @ Wo2[32x8192]  (Wo2[d][(c,Rj(f))] = Wo[c*32+d][f]).
// Grid (2 mt, 64 nt) = 128 CTAs, tile M=128 x N=128, 8 warps, warp 32x64.
// Wo window converted fp32->fp16 in-kernel into smem with Rj baked in.
#define LDW 136   // u16 per B_s row (272 B; 272 mod 128 = 16 -> ldsm conflict-free)

__global__ void __launch_bounds__(256, 2) k_makeTmma(const float* __restrict__ Wo) {
    __shared__ __align__(16) u16 B_s[32 * LDW];

    int mt = blockIdx.x;       // 0..1   (b-rows 128 each)
    int nt = blockIdx.y;       // 0..63  (128-col windows of 8192)
    int t = threadIdx.x, w = t >> 5, lane = t & 31;
    int g = lane >> 2, tig = lane & 3;
    int wm = w & 3, wn = w >> 2;            // warp tile: rows wm*32, cols wn*64
    int m0 = wm * 32, n0 = wn * 64;

    int c  = nt >> 1;                       // Wo row group
    int fb_half = (nt & 1) * 128;           // f half-window

    // --- A fragments (right): 4x LDG.128, canonical a-frag layout ---
    u32 af[2][2][4];
    {
        const uint4* A4 = (const uint4*)g_RhH;
        #pragma unroll
        for (int mi = 0; mi < 2; mi++) {
            int row = mt * 128 + m0 + mi * 16 + g;
            uint4 v0 = A4[row * 4 + tig];
            uint4 v1 = A4[(row + 8) * 4 + tig];
            af[0][mi][0] = v0.x; af[0][mi][2] = v0.y;
            af[1][mi][0] = v0.z; af[1][mi][2] = v0.w;
            af[0][mi][1] = v1.x; af[0][mi][3] = v1.y;
            af[1][mi][1] = v1.z; af[1][mi][3] = v1.w;
        }
    }

    // --- B_s fill: Wo[(c*32+d)][fb..fb+16) fp32 -> fp16 at Rj-local cols ---
    {
        int d = t >> 3, j = t & 7;
        const float4* src = (const float4*)(Wo + ((size_t)(c * 32 + d)) * 256 + fb_half + j * 16);
        float4 v0 = src[0], v1 = src[1], v2 = src[2], v3 = src[3];
        float vv[16] = {v0.x, v0.y, v0.z, v0.w, v1.x, v1.y, v1.z, v1.w,
                        v2.x, v2.y, v2.z, v2.w, v3.x, v3.y, v3.z, v3.w};
        #pragma unroll
        for (int u = 0; u < 8; u++) {
            __half2 h2 = __floats2half2_rn(vv[2 * u], vv[2 * u + 1]);
            int rloc = ((u & 1) << 3) | (((u >> 1) & 3) << 1);   // rjpos of f=2u within 16-block
            *(u32*)&B_s[d * LDW + j * 16 + rloc] = *(u32*)&h2;
        }
    }
    __syncthreads();

    float acc[2][8][4];
    #pragma unroll
    for (int mi = 0; mi < 2; mi++)
        #pragma unroll
        for (int ni = 0; ni < 8; ni++)
            #pragma unroll
            for (int q = 0; q < 4; q++) acc[mi][ni][q] = 0.f;

    u32 sbase = smem_u32(B_s);
    #pragma unroll
    for (int kb = 0; kb < 2; kb++) {
        u32 rowaddr = sbase + ((kb * 16 + (lane & 15)) * LDW) * 2;
        u32 bfr[8][2];
        #pragma unroll
        for (int ni = 0; ni < 8; ni++)
            ldsm_x2_t(bfr[ni][0], bfr[ni][1], rowaddr + (n0 + ni * 8) * 2);
        #pragma unroll
        for (int mi = 0; mi < 2; mi++)
            #pragma unroll
            for (int ni = 0; ni < 8; ni++)
                mma_f16(acc[mi][ni], af[kb][mi], bfr[ni]);
    }

    // --- epilogue: half2 stores straight into g_Bh (output IS rj-space) ---
    #pragma unroll
    for (int mi = 0; mi < 2; mi++) {
        int row = mt * 128 + m0 + mi * 16 + g;
        __half* p0 = g_Bh + (size_t)row * 8192 + nt * 128;
        __half* p1 = p0 + 8 * 8192;
        #pragma unroll
        for (int ni = 0; ni < 8; ni++) {
            int col = n0 + ni * 8 + tig * 2;
            __half2 h0 = __floats2half2_rn(acc[mi][ni][0], acc[mi][ni][1]);
            __half2 h1 = __floats2half2_rn(acc[mi][ni][2], acc[mi][ni][3]);
            *(__half2*)(p0 + col) = h0;
            *(__half2*)(p1 + col) = h1;
        }
    }
}

// ---------------- Kernel C: fp16 mma.sync GEMM with ldmatrix B ----------------
// (unchanged from R16 — proven 26.9us config)
#define LDBp 72   // u16 per row (144 B: ldsm conflict-free)

__global__ void __launch_bounds__(256, 3) k_gemm(const float* __restrict__ bo,
                                                 float* __restrict__ out) {
    __shared__ __align__(16) u16 B_s[32 * LDBp];

    int b  = blockIdx.x;
    int mt = blockIdx.y;
    int nt = blockIdx.z;
    int t = threadIdx.x, w = t >> 5, lane = t & 31;
    int g = lane >> 2, tig = lane & 3;
    int wm = w & 3, wn = w >> 2;
    int m0 = wm * 32, n0 = wn * 32;

    // --- A fragments: 4x LDG.128, fully coalesced ---
    u32 af[2][2][4];
    {
        const uint4* A4 = (const uint4*)g_Ah;
        #pragma unroll
        for (int mi = 0; mi < 2; mi++) {
            int row = mt * 128 + m0 + mi * 16 + g;
            uint4 v0 = A4[row * 4 + tig];
            uint4 v1 = A4[(row + 8) * 4 + tig];
            af[0][mi][0] = v0.x; af[0][mi][2] = v0.y;
            af[1][mi][0] = v0.z; af[1][mi][2] = v0.w;
            af[0][mi][1] = v1.x; af[0][mi][3] = v1.y;
            af[1][mi][1] = v1.z; af[1][mi][3] = v1.w;
        }
    }

    // --- B tile: straight copy, 1 LDG.128 + 1 STS.128 per thread ---
    {
        int cc = t >> 3, q = t & 7;
        uint4 v = *(const uint4*)(g_Bh + ((size_t)b * C_DIM + cc) * F_DIM + nt * 64 + q * 8);
        *(uint4*)&B_s[cc * LDBp + q * 8] = v;
    }

    float4 bv0 = __ldg((const float4*)&bo[nt * 64 + (wn * 2) * 16 + tig * 4]);
    float4 bv1 = __ldg((const float4*)&bo[nt * 64 + (wn * 2 + 1) * 16 + tig * 4]);
    __syncthreads();

    float acc[2][4][4];
    #pragma unroll
    for (int mi = 0; mi < 2; mi++)
        #pragma unroll
        for (int ni = 0; ni < 4; ni++)
            #pragma unroll
            for (int q = 0; q < 4; q++) acc[mi][ni][q] = 0.f;

    u32 sbase = smem_u32(B_s);
    #pragma unroll
    for (int kb = 0; kb < 2; kb++) {
        u32 rowaddr = sbase + ((kb * 16 + (lane & 15)) * LDBp) * 2;
        u32 bfr[4][2];
        #pragma unroll
        for (int ni = 0; ni < 4; ni++)
            ldsm_x2_t(bfr[ni][0], bfr[ni][1], rowaddr + (n0 + ni * 8) * 2);
        #pragma unroll
        for (int mi = 0; mi < 2; mi++)
            #pragma unroll
            for (int ni = 0; ni < 4; ni++)
                mma_f16(acc[mi][ni], af[kb][mi], bfr[ni]);
    }

    // --- epilogue: STG.128 (.cs), thread (g,tig) owns f = (wn*2+p)*16 + 4*tig ---
    #pragma unroll
    for (int mi = 0; mi < 2; mi++) {
        size_t a_row = (size_t)mt * 128 + m0 + mi * 16 + g;
        float* prow  = out + a_row * ((size_t)A_NODES * F_DIM) + (size_t)b * F_DIM + nt * 64;
        float* prow8 = prow + 8 * ((size_t)A_NODES * F_DIM);
        #pragma unroll
        for (int p = 0; p < 2; p++) {
            int ni0 = 2 * p, ni1 = 2 * p + 1;
            int fl = (wn * 2 + p) * 16 + tig * 4;
            float4 bv = p ? bv1 : bv0;
            float4 w0, w1;
            w0.x = acc[mi][ni0][0] + bv.x; w0.y = acc[mi][ni0][1] + bv.y;
            w0.z = acc[mi][ni1][0] + bv.z; w0.w = acc[mi][ni1][1] + bv.w;
            w1.x = acc[mi][ni0][2] + bv.x; w1.y = acc[mi][ni0][3] + bv.y;
            w1.z = acc[mi][ni1][2] + bv.z; w1.w = acc[mi][ni1][3] + bv.w;
            stg_cs_128(prow + fl,  w0);
            stg_cs_128(prow8 + fl, w1);
        }
    }
}

// ---------------- launch ------------------------------------------------------
extern "C" void kernel_launch(void* const* d_in, const int* in_sizes, int n_in,
                              void* d_out, int out_size) {
    const float* nv   = (const float*)d_in[0];
    const float* mask = (const float*)d_in[1];
    const float* lns  = (const float*)d_in[2];
    const float* lnb  = (const float*)d_in[3];
    const float* Wl   = (const float*)d_in[4];
    const float* bl   = (const float*)d_in[5];
    const float* Wr   = (const float*)d_in[6];
    const float* br   = (const float*)d_in[7];
    const float* Wo   = (const float*)d_in[8];
    const float* bo   = (const float*)d_in[9];
    float* out = (float*)d_out;

    k_lnproj<<<A_NODES, 256>>>(nv, mask, lns, lnb, Wl, bl, Wr, br);
    k_makeTmma<<<dim3(2, 64), 256>>>(Wo);
    k_gemm<<<dim3(256, 2, 4), 256>>>(bo, out);
}